// round 15
// baseline (speedup 1.0000x reference)
#include <cuda_runtime.h>

// Exact L-inf nearest neighbor. THREE kernels (self-cleaning state):
//   bucket_k : resets g_fail_cnt; bins B points into fixed-K buckets via
//              atomicAdd rank; overflow -> global list every query scans.
//   fast_k   : 4 lanes/query. Chance 1: 3x3 cells + ovf sweep + wall bound.
//              Chance 2: ring 2 + 5x5 bound. Chance 3: ring 3 + 7x7 bound.
//              Residual failures compacted to a list. REDUX.SYNC reduces.
//   slow_k   : ONE BLOCK per failed query; brute force over all of B with
//              coalesced float4 SoA loads; then idle/finished threads zero
//              g_cnt and reset g_ovf_cnt for the NEXT graph replay (slow_k
//              never reads g_cnt -> race-free; stream order does the rest).
// u64 pack (d_bits<<32 | payload) with payload idx-major: min IS the
// lexicographic (d, idx) compare -> exact jnp.argmin first-index ties.
// Wall soundness: out-of-range B points clamp into edge cells, so a wall
// touching the grid edge is dropped; every unscanned point lies strictly
// beyond a remaining wall (EPS-strict accept).

#define G      128
#define HALO   3
#define GH     (G + 2 * HALO)             // 134
#define NH     (GH * GH)                  // 17956
#define K      8
#define X0     (-4.5f)
#define EXT    9.0f
#define H      (EXT / (float)G)           // 0.0703125, binary exact
#define INVH   ((float)G / EXT)
#define EPS    1e-6f
#define SLOW_BLOCKS 512

__device__ int    g_cnt[NH];              // zero-init; re-zeroed by slow_k
__device__ float4 g_bkt[NH * K];
__device__ int    g_ovf_cnt;
__device__ float4 g_ovf[4096];
__device__ int    g_fail_cnt;
__device__ int    g_fail_q[32768];

__device__ __forceinline__ int cell_coord(float v) {
    int c = __float2int_rd((v - X0) * INVH);
    return min(max(c, 0), G - 1);
}

// lexicographic (d, payload) min over a lane group via 2x REDUX.SYNC
__device__ __forceinline__ unsigned long long
group_min(unsigned mask, unsigned long long best)
{
    unsigned db = (unsigned)(best >> 32), pb = (unsigned)best;
    unsigned dmin = __reduce_min_sync(mask, db);
    unsigned pmin = __reduce_min_sync(mask, (db == dmin) ? pb : 0xFFFFFFFFu);
    return (((unsigned long long)dmin) << 32) | pmin;
}

// ---------------- build ----------------
__global__ void __launch_bounds__(256)
bucket_k(const float* __restrict__ B, int N)
{
    int n = blockIdx.x * 256 + threadIdx.x;
    if (n == 0) g_fail_cnt = 0;           // consumed later this replay
    if (n >= N) return;
    float x = __ldg(&B[n]), y = __ldg(&B[N + n]);
    int h = (cell_coord(y) + HALO) * GH + (cell_coord(x) + HALO);
    int rank = atomicAdd(&g_cnt[h], 1);
    if (rank < K) {
        int pos = h * K + rank;
        unsigned pay = ((unsigned)n << 19) | (unsigned)pos;
        g_bkt[pos] = make_float4(x, y, __uint_as_float(pay), 0.0f);
    } else {
        int o = atomicAdd(&g_ovf_cnt, 1);
        unsigned pay = ((unsigned)n << 19) | (1u << 18) | (unsigned)o;
        g_ovf[o] = make_float4(x, y, __uint_as_float(pay), 0.0f);
    }
}

// ---------------- fast-path helpers ----------------
__device__ __forceinline__ void eval_pt(float4 pt, float ax, float ay,
                                        unsigned long long& best)
{
    float d = fmaxf(fabsf(ax - pt.x), fabsf(ay - pt.y));
    unsigned long long c = (((unsigned long long)__float_as_uint(d)) << 32)
                         | (unsigned long long)__float_as_uint(pt.z);
    best = min(best, c);
}

__device__ __forceinline__ void scan_hcell(int h, float ax, float ay,
                                           unsigned long long& best)
{
    int cnt = min(__ldg(&g_cnt[h]), K);
    const float4* bp = &g_bkt[h * K];
    for (int j = 0; j < cnt; ++j) eval_pt(__ldg(&bp[j]), ax, ay, best);
}

__device__ __forceinline__ float wall_bound(float ax, float ay,
                                            int cx, int cy, int r)
{
    float mb = __int_as_float(0x7f800000);
    if (cx - r > 0)     mb = fminf(mb, ax - (X0 + (float)(cx - r) * H));
    if (cx + r < G - 1) mb = fminf(mb, (X0 + (float)(cx + r + 1) * H) - ax);
    if (cy - r > 0)     mb = fminf(mb, ay - (X0 + (float)(cy - r) * H));
    if (cy + r < G - 1) mb = fminf(mb, (X0 + (float)(cy + r + 1) * H) - ay);
    return mb;
}

// ---------------- fast kernel: 4 lanes/query ----------------
__global__ void __launch_bounds__(256, 8)
fast_k(const float* __restrict__ A, float* __restrict__ out, int Q)
{
    const int tid  = blockIdx.x * 256 + threadIdx.x;
    const int q    = tid >> 2;
    const int lane = tid & 3;
    if (q >= Q) return;

    const unsigned gmask = 0xFu << (threadIdx.x & 28);

    const float2 aq = __ldg(&((const float2*)A)[q]);
    const float ax = aq.x, ay = aq.y;
    const int cx = cell_coord(ax);
    const int cy = cell_coord(ay);
    const int hc = (cy + HALO) * GH + (cx + HALO);

    unsigned long long best = 0xFFFFFFFFFFFFFFFFull;

    {   // chance 1: 3x3 cells, cell-per-lane
        int c1 = lane, c2 = lane + 4;
        int h1 = hc + (c1 / 3 - 1) * GH + (c1 % 3 - 1);
        int h2 = hc + (c2 / 3 - 1) * GH + (c2 % 3 - 1);
        scan_hcell(h1, ax, ay, best);
        scan_hcell(h2, ax, ay, best);
        if (lane == 0) scan_hcell(hc + GH + 1, ax, ay, best);
    }
    {   // overflow sweep
        int oc = g_ovf_cnt;
        for (int o = lane; o < oc; o += 4)
            eval_pt(__ldg(&g_ovf[o]), ax, ay, best);
    }
    best = group_min(gmask, best);

    bool ok = __uint_as_float((unsigned)(best >> 32))
              <= wall_bound(ax, ay, cx, cy, 1) - EPS;

    if (!ok) {   // chance 2: ring 2 (16 cells, 4/lane)
        #pragma unroll
        for (int k = 0; k < 4; ++k) {
            int tc = lane * 4 + k;
            int di, dj;
            if (tc < 5)       { di = tc - 2; dj = -2; }
            else if (tc < 10) { di = tc - 7; dj =  2; }
            else { int t2 = tc - 10; dj = (t2 >> 1) - 1; di = (t2 & 1) ? 2 : -2; }
            scan_hcell(hc + dj * GH + di, ax, ay, best);
        }
        best = group_min(gmask, best);
        ok = __uint_as_float((unsigned)(best >> 32))
             <= wall_bound(ax, ay, cx, cy, 2) - EPS;

        if (!ok) {   // chance 3: ring 3 (24 cells, 6/lane)
            #pragma unroll
            for (int k = 0; k < 6; ++k) {
                int tc = lane * 6 + k;
                int di, dj;
                if (tc < 7)       { di = tc - 3;  dj = -3; }
                else if (tc < 14) { di = tc - 10; dj =  3; }
                else { int t2 = tc - 14; dj = (t2 >> 1) - 2; di = (t2 & 1) ? 3 : -3; }
                scan_hcell(hc + dj * GH + di, ax, ay, best);
            }
            best = group_min(gmask, best);
            ok = __uint_as_float((unsigned)(best >> 32))
                 <= wall_bound(ax, ay, cx, cy, 3) - EPS;
        }
    }

    if (lane == 0) {
        if (ok) {
            unsigned pay = (unsigned)best;
            int pos = (int)(pay & 0x3FFFFu);
            float4 pt = (pay & (1u << 18)) ? __ldg(&g_ovf[pos])
                                           : __ldg(&g_bkt[pos]);
            ((float2*)out)[q] = make_float2(ax - pt.x, ay - pt.y);
        } else {
            int slot = atomicAdd(&g_fail_cnt, 1);
            g_fail_q[slot] = q;
        }
    }
}

// ---------------- slow kernel: ONE BLOCK per failed query + cleanup -----
__global__ void __launch_bounds__(256)
slow_k(const float* __restrict__ A, const float* __restrict__ B,
       float* __restrict__ out, int N)
{
    __shared__ unsigned long long s_best[8];

    const int cnt  = g_fail_cnt;
    const int t    = threadIdx.x;
    const int lane = t & 31;
    const int wid  = t >> 5;

    const int Nvec = (N & 3) ? 0 : (N & ~1023);    // multiple of 1024
    const float4* __restrict__ Bx4 = (const float4*)B;
    const float4* __restrict__ By4 = (const float4*)(B + N);

    for (int f = blockIdx.x; f < cnt; f += gridDim.x) {
        __syncthreads();                           // s_best reuse guard
        const int q = g_fail_q[f];
        const float2 aq = __ldg(&((const float2*)A)[q]);
        const float ax = aq.x, ay = aq.y;

        unsigned long long best = 0xFFFFFFFFFFFFFFFFull;

        for (int k = 0; k * 1024 < Nvec; ++k) {
            int i4 = t + (k << 8);
            float4 xs = __ldg(&Bx4[i4]);
            float4 ys = __ldg(&By4[i4]);
            int n0 = i4 << 2;
            float d0 = fmaxf(fabsf(ax - xs.x), fabsf(ay - ys.x));
            float d1 = fmaxf(fabsf(ax - xs.y), fabsf(ay - ys.y));
            float d2 = fmaxf(fabsf(ax - xs.z), fabsf(ay - ys.z));
            float d3 = fmaxf(fabsf(ax - xs.w), fabsf(ay - ys.w));
            best = min(best, (((unsigned long long)__float_as_uint(d0)) << 32) | (unsigned)(n0));
            best = min(best, (((unsigned long long)__float_as_uint(d1)) << 32) | (unsigned)(n0 + 1));
            best = min(best, (((unsigned long long)__float_as_uint(d2)) << 32) | (unsigned)(n0 + 2));
            best = min(best, (((unsigned long long)__float_as_uint(d3)) << 32) | (unsigned)(n0 + 3));
        }
        for (int n = Nvec + t; n < N; n += 256) {
            float d = fmaxf(fabsf(ax - __ldg(&B[n])), fabsf(ay - __ldg(&B[N + n])));
            best = min(best, (((unsigned long long)__float_as_uint(d)) << 32) | (unsigned)n);
        }

        best = group_min(0xffffffffu, best);
        if (lane == 0) s_best[wid] = best;
        __syncthreads();

        if (wid == 0) {
            best = (lane < 8) ? s_best[lane] : 0xFFFFFFFFFFFFFFFFull;
            best = group_min(0xffffffffu, best);
            if (lane == 0) {
                int nb = (int)(best & 0xFFFFFFFFu);
                ((float2*)out)[q] = make_float2(ax - __ldg(&B[nb]),
                                                ay - __ldg(&B[N + nb]));
            }
        }
    }

    // ---- cleanup for the NEXT replay (slow_k never reads g_cnt) ----
    for (int i = blockIdx.x * 256 + t; i < NH; i += gridDim.x * 256)
        g_cnt[i] = 0;
    if (blockIdx.x == 0 && t == 0) g_ovf_cnt = 0;
}

extern "C" void kernel_launch(void* const* d_in, const int* in_sizes, int n_in,
                              void* d_out, int out_size)
{
    const float* A = (const float*)d_in[0];   // [Q, 2]
    const float* B = (const float*)d_in[1];   // [2, N]
    float*     out = (float*)d_out;           // [Q, 2]

    const int Q = in_sizes[0] / 2;
    const int N = in_sizes[1] / 2;

    bucket_k<<<(N + 255) / 256, 256>>>(B, N);
    fast_k<<<(Q * 4 + 255) / 256, 256>>>(A, out, Q);
    slow_k<<<SLOW_BLOCKS, 256>>>(A, B, out, N);
}